// round 8
// baseline (speedup 1.0000x reference)
#include <cuda_runtime.h>
#include <math.h>
#include <stdint.h>

#define NB 8
#define NTOK 1024
#define CC2 512
#define KVD 1792
#define NH 4
#define NMAPS (NB*NH)          // 32
#define MAPELEMS (CC2*KVD)     // 917504
#define NPART (NMAPS*56)       // 56 tiles per map (14 x 4)

// ---------------- scratch ----------------
__device__ __align__(128) float g_X   [NB*NTOK*KVD];
__device__ __align__(128) float g_XT  [NB*KVD*NTOK];
__device__ __align__(128) float g_cx2 [NB*NTOK*CC2];
__device__ __align__(128) float g_c2T [NB*CC2*NTOK];
__device__ __align__(128) float g_Gt  [NB*KVD*CC2];
__device__ __align__(128) float g_T   [NMAPS*CC2*KVD];
__device__ __align__(128) float g_S   [NMAPS*CC2*KVD];
__device__ __align__(128) float g_Mt  [NB*CC2*KVD];
__device__ __align__(128) float g_ctx [NB*NTOK*CC2];
__device__ __align__(128) float g_res [NB*NTOK*CC2];
__device__ __align__(128) float g_x2  [NB*NTOK*CC2];
__device__ __align__(128) float g_h1  [NB*NTOK*CC2*4];
__device__ __align__(128) float g_WqT [NH*CC2*CC2];
__device__ __align__(128) float g_WkT [NH*KVD*KVD];
__device__ __align__(128) float g_WoutT[CC2*CC2];
__device__ __align__(128) float g_fc1T[CC2*4*CC2];
__device__ __align__(128) float g_fc2T[CC2*CC2*4];
__device__ __align__(128) float g_part[NPART*2];

// ---------------- helpers ----------------
__device__ __forceinline__ uint32_t smem_u32(const void* p) {
    uint32_t a;
    asm("{ .reg .u64 t; cvta.to.shared.u64 t, %1; cvt.u32.u64 %0, t; }" : "=r"(a) : "l"(p));
    return a;
}
#define CP_ASYNC16(sa, ga) \
    asm volatile("cp.async.cg.shared.global [%0], [%1], 16;" :: "r"(sa), "l"(ga) : "memory")
#define CP_COMMIT() asm volatile("cp.async.commit_group;" ::: "memory")
#define CP_WAIT2()  asm volatile("cp.async.wait_group 2;" ::: "memory")

__device__ __forceinline__ void mma_tf32(float* c, const uint32_t* a, const uint32_t* b) {
    asm volatile(
        "mma.sync.aligned.m16n8k8.row.col.f32.tf32.tf32.f32 "
        "{%0,%1,%2,%3}, {%4,%5,%6,%7}, {%8,%9}, {%0,%1,%2,%3};"
        : "+f"(c[0]), "+f"(c[1]), "+f"(c[2]), "+f"(c[3])
        : "r"(a[0]), "r"(a[1]), "r"(a[2]), "r"(a[3]), "r"(b[0]), "r"(b[1]));
}

// ---------------- tensor-core GEMM (unchanged from R7 winner) --------------
#define BM 128
#define BN 128
#define PAD 36
#define SM_BUF (128*PAD)
#define NSTAGE 3
#define SM_TOTAL (NSTAGE*2*SM_BUF*4)  // 110592 bytes

struct TCP {
    const float *A, *B; float *C;
    int lda, ldb, ldc, K;
    long sA, sB, sC;
    int aSel, bSel, nseg;
    long segA, segB;
    float alpha;
    const float* bias;
    const float* add; int ldAdd; long sAdd;
    float* part;
};

// EPI: 0 plain; 1 bias+gelu; 2 (+bias)+add; 3 plain + per-CTA IN partial stats
template <int EPI>
__global__ void __launch_bounds__(128, 2) gemm_mma(TCP p)
{
    extern __shared__ float sm[];
    uint32_t sb = smem_u32(sm);

    int t = threadIdx.x, lane = t & 31, w = t >> 5;
    int z = blockIdx.z;
    int m0 = blockIdx.y * BM, n0 = blockIdx.x * BN;
    int az = p.aSel == 0 ? z : (p.aSel == 1 ? (z & 3) : (z >> 2));
    int bz = p.bSel == 0 ? z : (p.bSel == 1 ? (z & 3) : (z >> 2));
    const float* Ab = p.A + (long)az * p.sA + (size_t)m0 * p.lda;
    const float* Bb = p.B + (long)bz * p.sB + (size_t)n0 * p.ldb;
    float* Cz = p.C + (long)z * p.sC;

    int kIters = p.K >> 5;
    int nIt = kIters * p.nseg;
    int seg = 0, kk = 0;

    auto issue = [&](int buf) {
        const float* Ag = Ab + (long)seg * p.segA + kk;
        const float* Bg = Bb + (long)seg * p.segB + kk;
        uint32_t da = sb + (2 * buf) * SM_BUF * 4;
        uint32_t db = sb + (2 * buf + 1) * SM_BUF * 4;
        #pragma unroll
        for (int i = 0; i < 8; i++) {
            int task = t + i * 128, row = task >> 3, q = task & 7;
            CP_ASYNC16(da + (row * PAD + q * 4) * 4, Ag + (size_t)row * p.lda + q * 4);
            CP_ASYNC16(db + (row * PAD + q * 4) * 4, Bg + (size_t)row * p.ldb + q * 4);
        }
        CP_COMMIT();
        kk += 32; if (kk == p.K) { kk = 0; seg++; }
    };

    issue(0);
    if (nIt > 1) issue(1);

    int wm = (w >> 1) * 64, wn = (w & 1) * 64;
    float acc[4][8][4] = {};
    int arowL = wm + (lane >> 2), browL = wn + (lane >> 2);

    for (int it = 0; it < nIt; it++) {
        int buf = it % NSTAGE;
        if (it + 2 < nIt) issue((it + 2) % NSTAGE);
        else CP_COMMIT();
        CP_WAIT2();
        __syncthreads();

        const uint32_t* Ai = (const uint32_t*)(sm + (2 * buf) * SM_BUF);
        const uint32_t* Bi = (const uint32_t*)(sm + (2 * buf + 1) * SM_BUF);
        #pragma unroll
        for (int ks = 0; ks < 4; ks++) {
            int ac = ks * 8 + (lane & 3);
            uint32_t a[4][4], b[8][2];
            #pragma unroll
            for (int mi = 0; mi < 4; mi++) {
                const uint32_t* p0 = Ai + (size_t)(arowL + mi * 16) * PAD + ac;
                a[mi][0] = p0[0];
                a[mi][2] = p0[4];
                a[mi][1] = p0[8 * PAD];
                a[mi][3] = p0[8 * PAD + 4];
            }
            #pragma unroll
            for (int ni = 0; ni < 8; ni++) {
                const uint32_t* p0 = Bi + (size_t)(browL + ni * 8) * PAD + ac;
                b[ni][0] = p0[0];
                b[ni][1] = p0[4];
            }
            #pragma unroll
            for (int mi = 0; mi < 4; mi++)
                #pragma unroll
                for (int ni = 0; ni < 8; ni++)
                    mma_tf32(acc[mi][ni], a[mi], b[ni]);
        }
        __syncthreads();
    }

    // -------- epilogue --------
    float psum = 0.f, psq = 0.f;
    #pragma unroll
    for (int mi = 0; mi < 4; mi++) {
        #pragma unroll
        for (int ni = 0; ni < 8; ni++) {
            int r0 = m0 + wm + mi * 16 + (lane >> 2);
            int cc = n0 + wn + ni * 8 + (lane & 3) * 2;
            #pragma unroll
            for (int h = 0; h < 2; h++) {
                int gr = r0 + h * 8;
                float v0 = p.alpha * acc[mi][ni][h * 2 + 0];
                float v1 = p.alpha * acc[mi][ni][h * 2 + 1];
                if (EPI == 1) {
                    v0 += p.bias[cc]; v1 += p.bias[cc + 1];
                    v0 = 0.5f * v0 * (1.f + erff(v0 * 0.70710678118654752f));
                    v1 = 0.5f * v1 * (1.f + erff(v1 * 0.70710678118654752f));
                }
                if (EPI == 2) {
                    if (p.bias) { v0 += p.bias[cc]; v1 += p.bias[cc + 1]; }
                    const float* ap = p.add + (long)z * p.sAdd + (size_t)gr * p.ldAdd + cc;
                    float2 av = *(const float2*)ap;
                    v0 += av.x; v1 += av.y;
                }
                if (EPI == 3) { psum += v0 + v1; psq += v0 * v0 + v1 * v1; }
                *(float2*)&Cz[(size_t)gr * p.ldc + cc] = make_float2(v0, v1);
            }
        }
    }
    if (EPI == 3) {
        #pragma unroll
        for (int o = 16; o > 0; o >>= 1) {
            psum += __shfl_down_sync(0xffffffffu, psum, o);
            psq  += __shfl_down_sync(0xffffffffu, psq,  o);
        }
        __syncthreads();
        if (lane == 0) { sm[w] = psum; sm[8 + w] = psq; }
        __syncthreads();
        if (t == 0) {
            float s = 0.f, ss = 0.f;
            #pragma unroll
            for (int i = 0; i < 4; i++) { s += sm[i]; ss += sm[8 + i]; }
            int idx = (z * 4 + blockIdx.y) * 14 + blockIdx.x;
            p.part[idx * 2] = s;
            p.part[idx * 2 + 1] = ss;
        }
    }
}

// ---------------- transpose: 64x64 tiles, float4 both sides ----------------
__global__ void __launch_bounds__(256) transpose_kernel(
    const float* __restrict__ in, float* __restrict__ out, int rows, int cols)
{
    __shared__ float tile[64][65];
    long zo = (long)blockIdx.z * rows * cols;
    const float* ip = in + zo;
    float* op = out + zo;
    int c0 = blockIdx.x * 64, r0 = blockIdx.y * 64;
    int t = threadIdx.x;
    int tx = t & 15;       // float4 column index (0..15)
    int ty = t >> 4;       // row (0..15)
    #pragma unroll
    for (int i = 0; i < 4; i++) {
        int r = ty + i * 16;
        float4 v = *(const float4*)&ip[(size_t)(r0 + r) * cols + c0 + tx * 4];
        tile[r][tx * 4 + 0] = v.x;
        tile[r][tx * 4 + 1] = v.y;
        tile[r][tx * 4 + 2] = v.z;
        tile[r][tx * 4 + 3] = v.w;
    }
    __syncthreads();
    #pragma unroll
    for (int i = 0; i < 4; i++) {
        int c = ty + i * 16;   // output row = tile column
        float4 v;
        v.x = tile[tx * 4 + 0][c];
        v.y = tile[tx * 4 + 1][c];
        v.z = tile[tx * 4 + 2][c];
        v.w = tile[tx * 4 + 3][c];
        *(float4*)&op[(size_t)(c0 + c) * rows + r0 + tx * 4] = v;
    }
}

// ---------------- reductions ----------------
template <int NW>
__device__ __forceinline__ float bRSum(float v, float* sbuf) {
    #pragma unroll
    for (int o = 16; o > 0; o >>= 1) v += __shfl_down_sync(0xffffffffu, v, o);
    int lane = threadIdx.x & 31, w = threadIdx.x >> 5;
    if (lane == 0) sbuf[w] = v;
    __syncthreads();
    float tot = 0.f;
    #pragma unroll
    for (int i = 0; i < NW; i++) tot += sbuf[i];
    __syncthreads();
    return tot;
}

template <int NW>
__device__ __forceinline__ float bRMax(float v, float* sbuf) {
    #pragma unroll
    for (int o = 16; o > 0; o >>= 1) v = fmaxf(v, __shfl_xor_sync(0xffffffffu, v, o));
    int lane = threadIdx.x & 31, w = threadIdx.x >> 5;
    if (lane == 0) sbuf[w] = v;
    __syncthreads();
    float tot = -1e30f;
    #pragma unroll
    for (int i = 0; i < NW; i++) tot = fmaxf(tot, sbuf[i]);
    __syncthreads();
    return tot;
}

// ---------------- LN kernels (float4 gmem paths) ----------------
__global__ void __launch_bounds__(256) ln_all_kernel(
    const float* __restrict__ e1, const float* __restrict__ e2, const float* __restrict__ e3,
    const float* __restrict__ g1, const float* __restrict__ b1,
    const float* __restrict__ ga, const float* __restrict__ ba,
    float* __restrict__ X, float* __restrict__ cx2)
{
    __shared__ float4 xs4[448];          // KVD floats
    __shared__ float red[8];
    float* xs = (float*)xs4;
    int tok = blockIdx.x, t = threadIdx.x;
    const float4* p1 = (const float4*)(e1 + (size_t)tok * 256);
    const float4* p2 = (const float4*)(e2 + (size_t)tok * 512);
    const float4* p3 = (const float4*)(e3 + (size_t)tok * 1024);
    if (t < 64)  xs4[t] = p1[t];
    if (t < 128) xs4[64 + t] = p2[t];
    xs4[192 + t] = p3[t];
    __syncthreads();
    float s = 0.f, ss = 0.f, s2 = 0.f, ss2 = 0.f;
    for (int i = t; i < KVD; i += 256) { float x = xs[i]; s += x; ss += x * x; }
    for (int i = t; i < 512; i += 256) { float x = xs[256 + i]; s2 += x; ss2 += x * x; }
    s  = bRSum<8>(s,  red);
    ss = bRSum<8>(ss, red);
    s2 = bRSum<8>(s2, red);
    ss2= bRSum<8>(ss2,red);
    float m  = s * (1.f / KVD), r = rsqrtf(ss * (1.f / KVD) - m * m + 1e-6f);
    float m2 = s2 * (1.f / 512.f), r2 = rsqrtf(ss2 * (1.f / 512.f) - m2 * m2 + 1e-6f);
    float4* Xo = (float4*)(X + (size_t)tok * KVD);
    float4* co = (float4*)(cx2 + (size_t)tok * 512);
    const float4* ga4 = (const float4*)ga;
    const float4* ba4 = (const float4*)ba;
    for (int i = t; i < 448; i += 256) {
        float4 x = xs4[i], g = ga4[i], b = ba4[i];
        Xo[i] = make_float4((x.x - m) * r * g.x + b.x, (x.y - m) * r * g.y + b.y,
                            (x.z - m) * r * g.z + b.z, (x.w - m) * r * g.w + b.w);
    }
    if (t < 128) {
        float4 x = xs4[64 + t];
        float4 g = ((const float4*)g1)[t], b = ((const float4*)b1)[t];
        co[t] = make_float4((x.x - m2) * r2 * g.x + b.x, (x.y - m2) * r2 * g.y + b.y,
                            (x.z - m2) * r2 * g.z + b.z, (x.w - m2) * r2 * g.w + b.w);
    }
}

__global__ void __launch_bounds__(128) ln512_kernel(
    const float* __restrict__ in, const float* __restrict__ g, const float* __restrict__ b,
    float* __restrict__ out)
{
    __shared__ float red[4];
    int tok = blockIdx.x, t = threadIdx.x;
    float4 x = ((const float4*)(in + (size_t)tok * 512))[t];
    float s  = bRSum<4>(x.x + x.y + x.z + x.w, red);
    float ss = bRSum<4>(x.x * x.x + x.y * x.y + x.z * x.z + x.w * x.w, red);
    float m = s * (1.f / 512.f);
    float r = rsqrtf(ss * (1.f / 512.f) - m * m + 1e-6f);
    float4 gg = ((const float4*)g)[t], bb = ((const float4*)b)[t];
    ((float4*)(out + (size_t)tok * 512))[t] =
        make_float4((x.x - m) * r * gg.x + bb.x, (x.y - m) * r * gg.y + bb.y,
                    (x.z - m) * r * gg.z + bb.z, (x.w - m) * r * gg.w + bb.w);
}

// ---------------- softmax over KV (float4, 224 threads/row) ----------------
__global__ void __launch_bounds__(224) softmax_kernel(float* __restrict__ S,
                                                      const float* __restrict__ part)
{
    __shared__ float red[7];
    int row = blockIdx.x, t = threadIdx.x;
    int map = row >> 9;
    float s0 = 0.f, q0 = 0.f;
    const float2* pp = (const float2*)part + map * 56;
    #pragma unroll 8
    for (int i = 0; i < 56; i++) { float2 v = pp[i]; s0 += v.x; q0 += v.y; }
    float invn = 1.f / (float)MAPELEMS;
    float mean = s0 * invn;
    float r = rsqrtf(q0 * invn - mean * mean + 1e-5f);

    float4* p = (float4*)(S + (size_t)row * KVD);
    float4 v0 = p[t], v1 = p[t + 224];
    v0.x *= r; v0.y *= r; v0.z *= r; v0.w *= r;
    v1.x *= r; v1.y *= r; v1.z *= r; v1.w *= r;
    float mx = fmaxf(fmaxf(fmaxf(v0.x, v0.y), fmaxf(v0.z, v0.w)),
                     fmaxf(fmaxf(v1.x, v1.y), fmaxf(v1.z, v1.w)));
    mx = bRMax<7>(mx, red);
    v0.x = expf(v0.x - mx); v0.y = expf(v0.y - mx);
    v0.z = expf(v0.z - mx); v0.w = expf(v0.w - mx);
    v1.x = expf(v1.x - mx); v1.y = expf(v1.y - mx);
    v1.z = expf(v1.z - mx); v1.w = expf(v1.w - mx);
    float s = (v0.x + v0.y + v0.z + v0.w) + (v1.x + v1.y + v1.z + v1.w);
    s = bRSum<7>(s, red);
    float inv = 1.f / s;
    v0.x *= inv; v0.y *= inv; v0.z *= inv; v0.w *= inv;
    v1.x *= inv; v1.y *= inv; v1.z *= inv; v1.w *= inv;
    p[t] = v0; p[t + 224] = v1;
}

// ---------------- host ----------------
static inline TCP mkP(const float* A, const float* B, float* C,
                      int lda, int ldb, int ldc, int K,
                      long sA, long sB, long sC, int aSel, int bSel,
                      int nseg, long segA, long segB, float alpha,
                      const float* bias, const float* add, int ldAdd, long sAdd,
                      float* part = nullptr)
{
    TCP p; p.A = A; p.B = B; p.C = C; p.lda = lda; p.ldb = ldb; p.ldc = ldc; p.K = K;
    p.sA = sA; p.sB = sB; p.sC = sC; p.aSel = aSel; p.bSel = bSel;
    p.nseg = nseg; p.segA = segA; p.segB = segB; p.alpha = alpha;
    p.bias = bias; p.add = add; p.ldAdd = ldAdd; p.sAdd = sAdd; p.part = part;
    return p;
}

extern "C" void kernel_launch(void* const* d_in, const int* in_sizes, int n_in,
                              void* d_out, int out_size)
{
    const float* emb1   = (const float*)d_in[0];
    const float* emb2   = (const float*)d_in[1];
    const float* emb3   = (const float*)d_in[2];
    const float* Wq     = (const float*)d_in[3];
    const float* Wk     = (const float*)d_in[4];
    const float* Wv     = (const float*)d_in[5];
    const float* Wout   = (const float*)d_in[6];
    const float* ln1_g  = (const float*)d_in[7];
    const float* ln1_b  = (const float*)d_in[8];
    const float* lnall_g= (const float*)d_in[9];
    const float* lnall_b= (const float*)d_in[10];
    const float* lnffn_g= (const float*)d_in[11];
    const float* lnffn_b= (const float*)d_in[12];
    const float* fc1_w  = (const float*)d_in[13];
    const float* fc1_b  = (const float*)d_in[14];
    const float* fc2_w  = (const float*)d_in[15];
    const float* fc2_b  = (const float*)d_in[16];
    float* out = (float*)d_out;

    cudaFuncSetAttribute(gemm_mma<0>, cudaFuncAttributeMaxDynamicSharedMemorySize, SM_TOTAL);
    cudaFuncSetAttribute(gemm_mma<1>, cudaFuncAttributeMaxDynamicSharedMemorySize, SM_TOTAL);
    cudaFuncSetAttribute(gemm_mma<2>, cudaFuncAttributeMaxDynamicSharedMemorySize, SM_TOTAL);
    cudaFuncSetAttribute(gemm_mma<3>, cudaFuncAttributeMaxDynamicSharedMemorySize, SM_TOTAL);

    float *X,*XT,*cx2,*c2T,*Gt,*T,*S,*Mt,*ctx,*res,*x2,*h1;
    float *WqT,*WkT,*WoutT,*fc1T,*fc2T,*part;
    cudaGetSymbolAddress((void**)&X,    g_X);
    cudaGetSymbolAddress((void**)&XT,   g_XT);
    cudaGetSymbolAddress((void**)&cx2,  g_cx2);
    cudaGetSymbolAddress((void**)&c2T,  g_c2T);
    cudaGetSymbolAddress((void**)&Gt,   g_Gt);
    cudaGetSymbolAddress((void**)&T,    g_T);
    cudaGetSymbolAddress((void**)&S,    g_S);
    cudaGetSymbolAddress((void**)&Mt,   g_Mt);
    cudaGetSymbolAddress((void**)&ctx,  g_ctx);
    cudaGetSymbolAddress((void**)&res,  g_res);
    cudaGetSymbolAddress((void**)&x2,   g_x2);
    cudaGetSymbolAddress((void**)&h1,   g_h1);
    cudaGetSymbolAddress((void**)&WqT,  g_WqT);
    cudaGetSymbolAddress((void**)&WkT,  g_WkT);
    cudaGetSymbolAddress((void**)&WoutT,g_WoutT);
    cudaGetSymbolAddress((void**)&fc1T, g_fc1T);
    cudaGetSymbolAddress((void**)&fc2T, g_fc2T);
    cudaGetSymbolAddress((void**)&part, g_part);

    const long MAPSZ = (long)CC2 * KVD;
    const float inv_sqrt_kv = 1.f / sqrtf((float)KVD);

    // weight transposes (64x64 tiles)
    transpose_kernel<<<dim3(8,8,4),   256>>>(Wq, WqT, 512, 512);
    transpose_kernel<<<dim3(28,28,4), 256>>>(Wk, WkT, KVD, KVD);
    transpose_kernel<<<dim3(8,8,1),   256>>>(Wout, WoutT, 512, 512);
    transpose_kernel<<<dim3(32,8,1),  256>>>(fc1_w, fc1T, 512, 2048);
    transpose_kernel<<<dim3(8,32,1),  256>>>(fc2_w, fc2T, 2048, 512);

    // 1. LayerNorms + activation transposes
    ln_all_kernel<<<NB*NTOK, 256>>>(emb1, emb2, emb3, ln1_g, ln1_b,
                                    lnall_g, lnall_b, X, cx2);
    transpose_kernel<<<dim3(28,16,8), 256>>>(X, XT, NTOK, KVD);
    transpose_kernel<<<dim3(8,16,8),  256>>>(cx2, c2T, NTOK, 512);

    // 2. Gt[b][j][c] : M=KVD, N=512, K=1024
    gemm_mma<0><<<dim3(4,14,8), 128, SM_TOTAL>>>(
        mkP(XT, c2T, Gt, NTOK, NTOK, 512, NTOK,
            (long)KVD*NTOK, (long)512*NTOK, (long)KVD*512, 0, 0,
            1, 0, 0, 1.f, nullptr, nullptr, 0, 0));

    // 3. T[z][d][j] : M=512, N=KVD, K=512
    gemm_mma<0><<<dim3(14,4,32), 128, SM_TOTAL>>>(
        mkP(WqT, Gt, T, 512, 512, KVD, 512,
            (long)512*512, (long)KVD*512, MAPSZ, 1, 2,
            1, 0, 0, 1.f, nullptr, nullptr, 0, 0));

    // 4. S[z][d][k'] : M=512, N=KVD, K=KVD ; fused IN partial stats
    gemm_mma<3><<<dim3(14,4,32), 128, SM_TOTAL>>>(
        mkP(T, WkT, S, KVD, KVD, KVD, KVD,
            MAPSZ, (long)KVD*KVD, MAPSZ, 0, 1,
            1, 0, 0, inv_sqrt_kv, nullptr, nullptr, 0, 0, part));

    // 5. probs = softmax(rstd * S)
    softmax_kernel<<<NMAPS*512, 224>>>(S, part);

    // 6. Mt[b][c][j] : M=512, N=KVD, 4 segs over h
    gemm_mma<0><<<dim3(14,4,8), 128, SM_TOTAL>>>(
        mkP(S, Wv, Mt, KVD, KVD, KVD, KVD,
            4*MAPSZ, 0, (long)512*KVD, 0, 0,
            4, MAPSZ, (long)KVD*KVD, 0.25f, nullptr, nullptr, 0, 0));

    // 7. ctx[b][t][c] : M=1024, N=512, K=KVD
    gemm_mma<0><<<dim3(4,8,8), 128, SM_TOTAL>>>(
        mkP(X, Mt, ctx, KVD, KVD, 512, KVD,
            (long)NTOK*KVD, (long)512*KVD, (long)NTOK*512, 0, 0,
            1, 0, 0, 1.f, nullptr, nullptr, 0, 0));

    // 8. res = ctx @ Wout + emb2 : M=8192, N=512, K=512
    gemm_mma<2><<<dim3(4,64,1), 128, SM_TOTAL>>>(
        mkP(ctx, WoutT, res, 512, 512, 512, 512,
            0, 0, 0, 0, 0, 1, 0, 0, 1.f, nullptr, emb2, 512, 0));

    // 9. x2 = LN(res)
    ln512_kernel<<<NB*NTOK, 128>>>(res, lnffn_g, lnffn_b, x2);

    // 10. h1 = gelu(x2 @ fc1 + b1) : M=8192, N=2048, K=512
    gemm_mma<1><<<dim3(16,64,1), 128, SM_TOTAL>>>(
        mkP(x2, fc1T, h1, 512, 512, 2048, 512,
            0, 0, 0, 0, 0, 1, 0, 0, 1.f, fc1_b, nullptr, 0, 0));

    // 11. out = h1 @ fc2 + b2 + res : M=8192, N=512, K=2048
    gemm_mma<2><<<dim3(4,64,1), 128, SM_TOTAL>>>(
        mkP(h1, fc2T, out, 2048, 2048, 512, 2048,
            0, 0, 0, 0, 0, 1, 0, 0, 1.f, fc2_b, res, 512, 0));
}

// round 10
// speedup vs baseline: 1.5628x; 1.5628x over previous
#include <cuda_runtime.h>
#include <math.h>
#include <stdint.h>

#define NB 8
#define NTOK 1024
#define CC2 512
#define KVD 1792
#define NH 4
#define NMAPS (NB*NH)          // 32
#define MAPELEMS (CC2*KVD)     // 917504
#define NPART (NMAPS*56)       // 56 tiles per map (14 x 4)

// ---------------- scratch ----------------
__device__ __align__(128) float g_X   [NB*NTOK*KVD];
__device__ __align__(128) float g_cx2 [NB*NTOK*CC2];
__device__ __align__(128) float g_Gt  [NB*KVD*CC2];
__device__ __align__(128) float g_T   [NMAPS*CC2*KVD];
__device__ __align__(128) float g_S   [NMAPS*CC2*KVD];
__device__ __align__(128) float g_Mt  [NB*CC2*KVD];
__device__ __align__(128) float g_ctx [NB*NTOK*CC2];
__device__ __align__(128) float g_res [NB*NTOK*CC2];
__device__ __align__(128) float g_x2  [NB*NTOK*CC2];
__device__ __align__(128) float g_h1  [NB*NTOK*CC2*4];
__device__ __align__(128) float g_WqT [NH*CC2*CC2];
__device__ __align__(128) float g_WkT [NH*KVD*KVD];
__device__ __align__(128) float g_WoutT[CC2*CC2];
__device__ __align__(128) float g_fc1T[CC2*4*CC2];
__device__ __align__(128) float g_fc2T[CC2*CC2*4];
__device__ __align__(128) float g_part[NPART*2];

// ---------------- helpers ----------------
__device__ __forceinline__ uint32_t smem_u32(const void* p) {
    uint32_t a;
    asm("{ .reg .u64 t; cvta.to.shared.u64 t, %1; cvt.u32.u64 %0, t; }" : "=r"(a) : "l"(p));
    return a;
}
#define CP_ASYNC16(sa, ga) \
    asm volatile("cp.async.cg.shared.global [%0], [%1], 16;" :: "r"(sa), "l"(ga) : "memory")
#define CP_COMMIT() asm volatile("cp.async.commit_group;" ::: "memory")
#define CP_WAIT2()  asm volatile("cp.async.wait_group 2;" ::: "memory")

__device__ __forceinline__ void mma_tf32(float* c, const uint32_t* a, const uint32_t* b) {
    asm volatile(
        "mma.sync.aligned.m16n8k8.row.col.f32.tf32.tf32.f32 "
        "{%0,%1,%2,%3}, {%4,%5,%6,%7}, {%8,%9}, {%0,%1,%2,%3};"
        : "+f"(c[0]), "+f"(c[1]), "+f"(c[2]), "+f"(c[3])
        : "r"(a[0]), "r"(a[1]), "r"(a[2]), "r"(a[3]), "r"(b[0]), "r"(b[1]));
}

// ---------------- tensor-core GEMM (R7 winner, unchanged) ------------------
#define BM 128
#define BN 128
#define PAD 36
#define SM_BUF (128*PAD)
#define NSTAGE 3
#define SM_TOTAL (NSTAGE*2*SM_BUF*4)  // 110592 bytes

struct TCP {
    const float *A, *B; float *C;
    int lda, ldb, ldc, K;
    long sA, sB, sC;
    int aSel, bSel, nseg;
    long segA, segB;
    float alpha;
    const float* bias;
    const float* add; int ldAdd; long sAdd;
    float* part;
};

// EPI: 0 plain; 1 bias+gelu; 2 (+bias)+add; 3 plain + per-CTA IN partial stats
template <int EPI>
__global__ void __launch_bounds__(128, 2) gemm_mma(TCP p)
{
    extern __shared__ float sm[];
    uint32_t sb = smem_u32(sm);

    int t = threadIdx.x, lane = t & 31, w = t >> 5;
    int z = blockIdx.z;
    int m0 = blockIdx.y * BM, n0 = blockIdx.x * BN;
    int az = p.aSel == 0 ? z : (p.aSel == 1 ? (z & 3) : (z >> 2));
    int bz = p.bSel == 0 ? z : (p.bSel == 1 ? (z & 3) : (z >> 2));
    const float* Ab = p.A + (long)az * p.sA + (size_t)m0 * p.lda;
    const float* Bb = p.B + (long)bz * p.sB + (size_t)n0 * p.ldb;
    float* Cz = p.C + (long)z * p.sC;

    int kIters = p.K >> 5;
    int nIt = kIters * p.nseg;
    int seg = 0, kk = 0;

    auto issue = [&](int buf) {
        const float* Ag = Ab + (long)seg * p.segA + kk;
        const float* Bg = Bb + (long)seg * p.segB + kk;
        uint32_t da = sb + (2 * buf) * SM_BUF * 4;
        uint32_t db = sb + (2 * buf + 1) * SM_BUF * 4;
        #pragma unroll
        for (int i = 0; i < 8; i++) {
            int task = t + i * 128, row = task >> 3, q = task & 7;
            CP_ASYNC16(da + (row * PAD + q * 4) * 4, Ag + (size_t)row * p.lda + q * 4);
            CP_ASYNC16(db + (row * PAD + q * 4) * 4, Bg + (size_t)row * p.ldb + q * 4);
        }
        CP_COMMIT();
        kk += 32; if (kk == p.K) { kk = 0; seg++; }
    };

    issue(0);
    if (nIt > 1) issue(1);

    int wm = (w >> 1) * 64, wn = (w & 1) * 64;
    float acc[4][8][4] = {};
    int arowL = wm + (lane >> 2), browL = wn + (lane >> 2);

    for (int it = 0; it < nIt; it++) {
        int buf = it % NSTAGE;
        if (it + 2 < nIt) issue((it + 2) % NSTAGE);
        else CP_COMMIT();
        CP_WAIT2();
        __syncthreads();

        const uint32_t* Ai = (const uint32_t*)(sm + (2 * buf) * SM_BUF);
        const uint32_t* Bi = (const uint32_t*)(sm + (2 * buf + 1) * SM_BUF);
        #pragma unroll
        for (int ks = 0; ks < 4; ks++) {
            int ac = ks * 8 + (lane & 3);
            uint32_t a[4][4], b[8][2];
            #pragma unroll
            for (int mi = 0; mi < 4; mi++) {
                const uint32_t* p0 = Ai + (size_t)(arowL + mi * 16) * PAD + ac;
                a[mi][0] = p0[0];
                a[mi][2] = p0[4];
                a[mi][1] = p0[8 * PAD];
                a[mi][3] = p0[8 * PAD + 4];
            }
            #pragma unroll
            for (int ni = 0; ni < 8; ni++) {
                const uint32_t* p0 = Bi + (size_t)(browL + ni * 8) * PAD + ac;
                b[ni][0] = p0[0];
                b[ni][1] = p0[4];
            }
            #pragma unroll
            for (int mi = 0; mi < 4; mi++)
                #pragma unroll
                for (int ni = 0; ni < 8; ni++)
                    mma_tf32(acc[mi][ni], a[mi], b[ni]);
        }
        __syncthreads();
    }

    // -------- epilogue --------
    float psum = 0.f, psq = 0.f;
    #pragma unroll
    for (int mi = 0; mi < 4; mi++) {
        #pragma unroll
        for (int ni = 0; ni < 8; ni++) {
            int r0 = m0 + wm + mi * 16 + (lane >> 2);
            int cc = n0 + wn + ni * 8 + (lane & 3) * 2;
            #pragma unroll
            for (int h = 0; h < 2; h++) {
                int gr = r0 + h * 8;
                float v0 = p.alpha * acc[mi][ni][h * 2 + 0];
                float v1 = p.alpha * acc[mi][ni][h * 2 + 1];
                if (EPI == 1) {
                    v0 += p.bias[cc]; v1 += p.bias[cc + 1];
                    v0 = 0.5f * v0 * (1.f + erff(v0 * 0.70710678118654752f));
                    v1 = 0.5f * v1 * (1.f + erff(v1 * 0.70710678118654752f));
                }
                if (EPI == 2) {
                    if (p.bias) { v0 += p.bias[cc]; v1 += p.bias[cc + 1]; }
                    const float* ap = p.add + (long)z * p.sAdd + (size_t)gr * p.ldAdd + cc;
                    float2 av = *(const float2*)ap;
                    v0 += av.x; v1 += av.y;
                }
                if (EPI == 3) { psum += v0 + v1; psq += v0 * v0 + v1 * v1; }
                *(float2*)&Cz[(size_t)gr * p.ldc + cc] = make_float2(v0, v1);
            }
        }
    }
    if (EPI == 3) {
        #pragma unroll
        for (int o = 16; o > 0; o >>= 1) {
            psum += __shfl_down_sync(0xffffffffu, psum, o);
            psq  += __shfl_down_sync(0xffffffffu, psq,  o);
        }
        __syncthreads();
        if (lane == 0) { sm[w] = psum; sm[8 + w] = psq; }
        __syncthreads();
        if (t == 0) {
            float s = 0.f, ss = 0.f;
            #pragma unroll
            for (int i = 0; i < 4; i++) { s += sm[i]; ss += sm[8 + i]; }
            int idx = (z * 4 + blockIdx.y) * 14 + blockIdx.x;
            p.part[idx * 2] = s;
            p.part[idx * 2 + 1] = ss;
        }
    }
}

// ---------------- TN GEMM: D[M,N] = sum_k A[k,m] * B[k,n] (both K-major) ---
// Used for Gt = X^T-contract: avoids materializing XT / c2T.
#define PADK 132
#define SM_BUF_TN (32*PADK)                 // 4224 floats per operand buffer
#define SM_TOTAL_TN (NSTAGE*2*SM_BUF_TN*4)  // 101376 bytes

__global__ void __launch_bounds__(128, 2) gemm_mma_tn(TCP p)
{
    extern __shared__ float sm[];
    uint32_t sb = smem_u32(sm);

    int t = threadIdx.x, lane = t & 31, w = t >> 5;
    int z = blockIdx.z;
    int m0 = blockIdx.y * BM, n0 = blockIdx.x * BN;
    const float* Ab = p.A + (long)z * p.sA + m0;   // column offset
    const float* Bb = p.B + (long)z * p.sB + n0;
    float* Cz = p.C + (long)z * p.sC;

    int nIt = p.K >> 5;
    int kk = 0;

    auto issue = [&](int buf) {
        const float* Ag = Ab + (size_t)kk * p.lda;
        const float* Bg = Bb + (size_t)kk * p.ldb;
        uint32_t da = sb + (2 * buf) * SM_BUF_TN * 4;
        uint32_t db = sb + (2 * buf + 1) * SM_BUF_TN * 4;
        #pragma unroll
        for (int i = 0; i < 8; i++) {
            int task = t + i * 128, kr = task >> 5, q = task & 31;
            CP_ASYNC16(da + (kr * PADK + q * 4) * 4, Ag + (size_t)kr * p.lda + q * 4);
            CP_ASYNC16(db + (kr * PADK + q * 4) * 4, Bg + (size_t)kr * p.ldb + q * 4);
        }
        CP_COMMIT();
        kk += 32;
    };

    issue(0);
    if (nIt > 1) issue(1);

    int wm = (w >> 1) * 64, wn = (w & 1) * 64;
    float acc[4][8][4] = {};
    int arowL = wm + (lane >> 2), browL = wn + (lane >> 2);

    for (int it = 0; it < nIt; it++) {
        int buf = it % NSTAGE;
        if (it + 2 < nIt) issue((it + 2) % NSTAGE);
        else CP_COMMIT();
        CP_WAIT2();
        __syncthreads();

        const uint32_t* Ai = (const uint32_t*)(sm + (2 * buf) * SM_BUF_TN);
        const uint32_t* Bi = (const uint32_t*)(sm + (2 * buf + 1) * SM_BUF_TN);
        #pragma unroll
        for (int ks = 0; ks < 4; ks++) {
            int ac = ks * 8 + (lane & 3);
            uint32_t a[4][4], b[8][2];
            #pragma unroll
            for (int mi = 0; mi < 4; mi++) {
                const uint32_t* p0 = Ai + (size_t)ac * PADK + arowL + mi * 16;
                a[mi][0] = p0[0];                 // (row, ac)
                a[mi][1] = p0[8];                 // (row+8, ac)
                a[mi][2] = p0[4 * PADK];          // (row, ac+4)
                a[mi][3] = p0[4 * PADK + 8];      // (row+8, ac+4)
            }
            #pragma unroll
            for (int ni = 0; ni < 8; ni++) {
                const uint32_t* p0 = Bi + (size_t)ac * PADK + browL + ni * 8;
                b[ni][0] = p0[0];
                b[ni][1] = p0[4 * PADK];
            }
            #pragma unroll
            for (int mi = 0; mi < 4; mi++)
                #pragma unroll
                for (int ni = 0; ni < 8; ni++)
                    mma_tf32(acc[mi][ni], a[mi], b[ni]);
        }
        __syncthreads();
    }

    #pragma unroll
    for (int mi = 0; mi < 4; mi++) {
        #pragma unroll
        for (int ni = 0; ni < 8; ni++) {
            int r0 = m0 + wm + mi * 16 + (lane >> 2);
            int cc = n0 + wn + ni * 8 + (lane & 3) * 2;
            #pragma unroll
            for (int h = 0; h < 2; h++) {
                int gr = r0 + h * 8;
                *(float2*)&Cz[(size_t)gr * p.ldc + cc] =
                    make_float2(acc[mi][ni][h * 2 + 0], acc[mi][ni][h * 2 + 1]);
            }
        }
    }
}

// ---------------- transpose (R7 proven 32x33) ----------------
__global__ void __launch_bounds__(256) transpose_kernel(
    const float* __restrict__ in, float* __restrict__ out, int rows, int cols)
{
    __shared__ float tile[32][33];
    long zo = (long)blockIdx.z * rows * cols;
    const float* ip = in + zo;
    float* op = out + zo;
    int c0 = blockIdx.x * 32, r0 = blockIdx.y * 32;
    int tx = threadIdx.x & 31, ty = threadIdx.x >> 5;
    #pragma unroll
    for (int i = 0; i < 4; i++)
        tile[ty + i * 8][tx] = ip[(size_t)(r0 + ty + i * 8) * cols + c0 + tx];
    __syncthreads();
    #pragma unroll
    for (int i = 0; i < 4; i++)
        op[(size_t)(c0 + ty + i * 8) * rows + r0 + tx] = tile[tx][ty + i * 8];
}

// ---------------- elementwise (R7 proven) ----------------
__device__ __forceinline__ float blockReduceSum(float v, float* sbuf) {
    #pragma unroll
    for (int o = 16; o > 0; o >>= 1) v += __shfl_down_sync(0xffffffffu, v, o);
    int lane = threadIdx.x & 31, w = threadIdx.x >> 5;
    if (lane == 0) sbuf[w] = v;
    __syncthreads();
    float tot = 0.f;
    #pragma unroll
    for (int i = 0; i < 8; i++) tot += sbuf[i];
    __syncthreads();
    return tot;
}

__global__ void __launch_bounds__(256) ln_all_kernel(
    const float* __restrict__ e1, const float* __restrict__ e2, const float* __restrict__ e3,
    const float* __restrict__ g1, const float* __restrict__ b1,
    const float* __restrict__ ga, const float* __restrict__ ba,
    float* __restrict__ X, float* __restrict__ cx2)
{
    __shared__ float xs[KVD];
    __shared__ float red[8];
    int tok = blockIdx.x, t = threadIdx.x;
    const float* p1 = e1 + (size_t)tok * 256;
    const float* p2 = e2 + (size_t)tok * 512;
    const float* p3 = e3 + (size_t)tok * 1024;
    xs[t] = p1[t];
    xs[256 + t] = p2[t];
    xs[512 + t] = p2[256 + t];
    #pragma unroll
    for (int i = 0; i < 4; i++) xs[768 + t + i * 256] = p3[t + i * 256];
    __syncthreads();
    float s = 0.f, ss = 0.f, s2 = 0.f, ss2 = 0.f;
    for (int i = t; i < KVD; i += 256) { float x = xs[i]; s += x; ss += x * x; }
    for (int i = t; i < 512; i += 256) { float x = xs[256 + i]; s2 += x; ss2 += x * x; }
    s  = blockReduceSum(s,  red);
    ss = blockReduceSum(ss, red);
    s2 = blockReduceSum(s2, red);
    ss2= blockReduceSum(ss2,red);
    float m  = s * (1.f / KVD), r = rsqrtf(ss * (1.f / KVD) - m * m + 1e-6f);
    float m2 = s2 * (1.f / 512.f), r2 = rsqrtf(ss2 * (1.f / 512.f) - m2 * m2 + 1e-6f);
    float* Xo = X + (size_t)tok * KVD;
    float* co = cx2 + (size_t)tok * 512;
    for (int i = t; i < KVD; i += 256) Xo[i] = (xs[i] - m) * r * ga[i] + ba[i];
    for (int i = t; i < 512; i += 256) co[i] = (xs[256 + i] - m2) * r2 * g1[i] + b1[i];
}

__global__ void __launch_bounds__(256) ln512_kernel(
    const float* __restrict__ in, const float* __restrict__ g, const float* __restrict__ b,
    float* __restrict__ out)
{
    __shared__ float red[8];
    int tok = blockIdx.x, t = threadIdx.x;
    const float* p = in + (size_t)tok * 512;
    float x0 = p[t], x1 = p[t + 256];
    float s = blockReduceSum(x0 + x1, red);
    float ss = blockReduceSum(x0 * x0 + x1 * x1, red);
    float m = s * (1.f / 512.f);
    float r = rsqrtf(ss * (1.f / 512.f) - m * m + 1e-6f);
    float* o = out + (size_t)tok * 512;
    o[t] = (x0 - m) * r * g[t] + b[t];
    o[t + 256] = (x1 - m) * r * g[t + 256] + b[t + 256];
}

__global__ void __launch_bounds__(256) softmax_kernel(float* __restrict__ S,
                                                      const float* __restrict__ part)
{
    __shared__ float red[8];
    int row = blockIdx.x, t = threadIdx.x;
    int map = row >> 9;
    float s0 = 0.f, q0 = 0.f;
    const float2* pp = (const float2*)part + map * 56;
    #pragma unroll 8
    for (int i = 0; i < 56; i++) { float2 v = pp[i]; s0 += v.x; q0 += v.y; }
    float invn = 1.f / (float)MAPELEMS;
    float mean = s0 * invn;
    float r = rsqrtf(q0 * invn - mean * mean + 1e-5f);

    float* p = S + (size_t)row * KVD;
    float v[7];
    float mx = -1e30f;
    #pragma unroll
    for (int j = 0; j < 7; j++) { v[j] = p[t + j * 256] * r; mx = fmaxf(mx, v[j]); }
    #pragma unroll
    for (int o = 16; o > 0; o >>= 1) mx = fmaxf(mx, __shfl_xor_sync(0xffffffffu, mx, o));
    int lane = t & 31, w = t >> 5;
    if (lane == 0) red[w] = mx;
    __syncthreads();
    float bm = red[0];
    #pragma unroll
    for (int i = 1; i < 8; i++) bm = fmaxf(bm, red[i]);
    __syncthreads();
    float s = 0.f;
    #pragma unroll
    for (int j = 0; j < 7; j++) { v[j] = expf(v[j] - bm); s += v[j]; }
    s = blockReduceSum(s, red);
    float inv = 1.f / s;
    #pragma unroll
    for (int j = 0; j < 7; j++) p[t + j * 256] = v[j] * inv;
}

// ---------------- host ----------------
static inline TCP mkP(const float* A, const float* B, float* C,
                      int lda, int ldb, int ldc, int K,
                      long sA, long sB, long sC, int aSel, int bSel,
                      int nseg, long segA, long segB, float alpha,
                      const float* bias, const float* add, int ldAdd, long sAdd,
                      float* part = nullptr)
{
    TCP p; p.A = A; p.B = B; p.C = C; p.lda = lda; p.ldb = ldb; p.ldc = ldc; p.K = K;
    p.sA = sA; p.sB = sB; p.sC = sC; p.aSel = aSel; p.bSel = bSel;
    p.nseg = nseg; p.segA = segA; p.segB = segB; p.alpha = alpha;
    p.bias = bias; p.add = add; p.ldAdd = ldAdd; p.sAdd = sAdd; p.part = part;
    return p;
}

extern "C" void kernel_launch(void* const* d_in, const int* in_sizes, int n_in,
                              void* d_out, int out_size)
{
    const float* emb1   = (const float*)d_in[0];
    const float* emb2   = (const float*)d_in[1];
    const float* emb3   = (const float*)d_in[2];
    const float* Wq     = (const float*)d_in[3];
    const float* Wk     = (const float*)d_in[4];
    const float* Wv     = (const float*)d_in[5];
    const float* Wout   = (const float*)d_in[6];
    const float* ln1_g  = (const float*)d_in[7];
    const float* ln1_b  = (const float*)d_in[8];
    const float* lnall_g= (const float*)d_in[9];
    const float* lnall_b= (const float*)d_in[10];
    const float* lnffn_g= (const float*)d_in[11];
    const float* lnffn_b= (const float*)d_in[12];
    const float* fc1_w  = (const float*)d_in[13];
    const float* fc1_b  = (const float*)d_in[14];
    const float* fc2_w  = (const float*)d_in[15];
    const float* fc2_b  = (const float*)d_in[16];
    float* out = (float*)d_out;

    cudaFuncSetAttribute(gemm_mma<0>, cudaFuncAttributeMaxDynamicSharedMemorySize, SM_TOTAL);
    cudaFuncSetAttribute(gemm_mma<1>, cudaFuncAttributeMaxDynamicSharedMemorySize, SM_TOTAL);
    cudaFuncSetAttribute(gemm_mma<2>, cudaFuncAttributeMaxDynamicSharedMemorySize, SM_TOTAL);
    cudaFuncSetAttribute(gemm_mma<3>, cudaFuncAttributeMaxDynamicSharedMemorySize, SM_TOTAL);
    cudaFuncSetAttribute(gemm_mma_tn, cudaFuncAttributeMaxDynamicSharedMemorySize, SM_TOTAL_TN);

    float *X,*cx2,*Gt,*T,*S,*Mt,*ctx,*res,*x2,*h1;
    float *WqT,*WkT,*WoutT,*fc1T,*fc2T,*part;
    cudaGetSymbolAddress((void**)&X,    g_X);
    cudaGetSymbolAddress((void**)&cx2,  g_cx2);
    cudaGetSymbolAddress((void**)&Gt,   g_Gt);
    cudaGetSymbolAddress((void**)&T,    g_T);
    cudaGetSymbolAddress((void**)&S,    g_S);
    cudaGetSymbolAddress((void**)&Mt,   g_Mt);
    cudaGetSymbolAddress((void**)&ctx,  g_ctx);
    cudaGetSymbolAddress((void**)&res,  g_res);
    cudaGetSymbolAddress((void**)&x2,   g_x2);
    cudaGetSymbolAddress((void**)&h1,   g_h1);
    cudaGetSymbolAddress((void**)&WqT,  g_WqT);
    cudaGetSymbolAddress((void**)&WkT,  g_WkT);
    cudaGetSymbolAddress((void**)&WoutT,g_WoutT);
    cudaGetSymbolAddress((void**)&fc1T, g_fc1T);
    cudaGetSymbolAddress((void**)&fc2T, g_fc2T);
    cudaGetSymbolAddress((void**)&part, g_part);

    const long MAPSZ = (long)CC2 * KVD;
    const float inv_sqrt_kv = 1.f / sqrtf((float)KVD);

    // weight transposes
    transpose_kernel<<<dim3(16,16,4), 256>>>(Wq, WqT, 512, 512);
    transpose_kernel<<<dim3(56,56,4), 256>>>(Wk, WkT, KVD, KVD);
    transpose_kernel<<<dim3(16,16,1), 256>>>(Wout, WoutT, 512, 512);
    transpose_kernel<<<dim3(64,16,1), 256>>>(fc1_w, fc1T, 512, 2048);
    transpose_kernel<<<dim3(16,64,1), 256>>>(fc2_w, fc2T, 2048, 512);

    // 1. LayerNorms (no activation transposes needed anymore)
    ln_all_kernel<<<NB*NTOK, 256>>>(emb1, emb2, emb3, ln1_g, ln1_b,
                                    lnall_g, lnall_b, X, cx2);

    // 2. Gt[b][j][c] = sum_t X[t,j] cx2[t,c] : TN form, M=KVD, N=512, K=1024
    gemm_mma_tn<<<dim3(4,14,8), 128, SM_TOTAL_TN>>>(
        mkP(X, cx2, Gt, KVD, 512, 512, NTOK,
            (long)NTOK*KVD, (long)NTOK*512, (long)KVD*512, 0, 0,
            1, 0, 0, 1.f, nullptr, nullptr, 0, 0));

    // 3. T[z][d][j] : M=512, N=KVD, K=512
    gemm_mma<0><<<dim3(14,4,32), 128, SM_TOTAL>>>(
        mkP(WqT, Gt, T, 512, 512, KVD, 512,
            (long)512*512, (long)KVD*512, MAPSZ, 1, 2,
            1, 0, 0, 1.f, nullptr, nullptr, 0, 0));

    // 4. S[z][d][k'] : M=512, N=KVD, K=KVD ; fused IN partial stats
    gemm_mma<3><<<dim3(14,4,32), 128, SM_TOTAL>>>(
        mkP(T, WkT, S, KVD, KVD, KVD, KVD,
            MAPSZ, (long)KVD*KVD, MAPSZ, 0, 1,
            1, 0, 0, inv_sqrt_kv, nullptr, nullptr, 0, 0, part));

    // 5. probs = softmax(rstd * S)
    softmax_kernel<<<NMAPS*512, 256>>>(S, part);

    // 6. Mt[b][c][j] : M=512, N=KVD, 4 segs over h
    gemm_mma<0><<<dim3(14,4,8), 128, SM_TOTAL>>>(
        mkP(S, Wv, Mt, KVD, KVD, KVD, KVD,
            4*MAPSZ, 0, (long)512*KVD, 0, 0,
            4, MAPSZ, (long)KVD*KVD, 0.25f, nullptr, nullptr, 0, 0));

    // 7. ctx[b][t][c] : M=1024, N=512, K=KVD
    gemm_mma<0><<<dim3(4,8,8), 128, SM_TOTAL>>>(
        mkP(X, Mt, ctx, KVD, KVD, 512, KVD,
            (long)NTOK*KVD, (long)512*KVD, (long)NTOK*512, 0, 0,
            1, 0, 0, 1.f, nullptr, nullptr, 0, 0));

    // 8. res = ctx @ Wout + emb2 : M=8192, N=512, K=512
    gemm_mma<2><<<dim3(4,64,1), 128, SM_TOTAL>>>(
        mkP(ctx, WoutT, res, 512, 512, 512, 512,
            0, 0, 0, 0, 0, 1, 0, 0, 1.f, nullptr, emb2, 512, 0));

    // 9. x2 = LN(res)
    ln512_kernel<<<NB*NTOK, 256>>>(res, lnffn_g, lnffn_b, x2);

    // 10. h1 = gelu(x2 @ fc1 + b1) : M=8192, N=2048, K=512
    gemm_mma<1><<<dim3(16,64,1), 128, SM_TOTAL>>>(
        mkP(x2, fc1T, h1, 512, 512, 2048, 512,
            0, 0, 0, 0, 0, 1, 0, 0, 1.f, fc1_b, nullptr, 0, 0));

    // 11. out = h1 @ fc2 + b2 + res : M=8192, N=512, K=2048
    gemm_mma<2><<<dim3(4,64,1), 128, SM_TOTAL>>>(
        mkP(h1, fc2T, out, 2048, 2048, 512, 2048,
            0, 0, 0, 0, 0, 1, 0, 0, 1.f, fc2_b, res, 512, 0));
}